// round 1
// baseline (speedup 1.0000x reference)
#include <cuda_runtime.h>
#include <math.h>

#define B 8
#define N 256
#define BN 2048
#define NID 64
#define V 128
#define GH 128
#define PHI 256
#define RHO 128
#define EPS 1e-5f

// ---------------- scratch (device globals; no allocation allowed) ----------------
__device__ float g_H[BN * GH];      // node features (V == GH == 128)
__device__ float g_H2[BN * GH];     // rgcn output
__device__ float g_agg[BN * GH];    // agg buffer
__device__ float g_phi[BN * PHI];   // phi output
__device__ float g_sums[2 * B * PHI]; // home_sum then away_sum

// ---------------- K1: embedding  H = relu(X@W1+b1)@W2 + b2 ----------------
__global__ void k_emb(const float* __restrict__ X,
                      const float* __restrict__ W1, const float* __restrict__ b1,
                      const float* __restrict__ W2, const float* __restrict__ b2) {
    int row = blockIdx.x;
    int t = threadIdx.x;            // 128 threads
    __shared__ float xs[NID];
    __shared__ float h1[V];
    if (t < NID) xs[t] = X[row * NID + t];
    __syncthreads();
    float acc = b1[t];
#pragma unroll 8
    for (int k = 0; k < NID; k++) acc = fmaf(xs[k], W1[k * V + t], acc);
    h1[t] = fmaxf(acc, 0.f);
    __syncthreads();
    float acc2 = b2[t];
#pragma unroll 8
    for (int k = 0; k < V; k++) acc2 = fmaf(h1[k], W2[k * V + t], acc2);
    g_H[row * V + t] = acc2;
}

// ---------------- K2: RGCN.  row = b*N+j (target node). ----------------
// rel = (w > 0): relation 0 <=> w < 0, relation 1 <=> w > 0 (w==0 invalid).
__global__ void k_rgcn(const float* __restrict__ A,
                       const float* __restrict__ Wrel,   // (2, V, GH)
                       const float* __restrict__ Wroot,  // (V, GH)
                       const float* __restrict__ bias) { // (GH,)
    int row = blockIdx.x;
    int b = row >> 8;
    int j = row & 255;
    int t = threadIdx.x;            // 128 threads
    __shared__ float s_neg[V], s_pos[V], hrow[V];

    const float* Ab = A + b * N * N;
    const float* Hb = g_H + b * N * V;

    float accN = 0.f, accP = 0.f, cN = 0.f, cP = 0.f;
    for (int i = 0; i < N; i++) {
        float a = Ab[i * N + j];    // broadcast within warp
        float h = Hb[i * V + t];    // coalesced
        if (a > 0.f) { accP += h; cP += 1.f; }
        else if (a < 0.f) { accN += h; cN += 1.f; }
    }
    s_neg[t] = accN / fmaxf(cN, 1.f);
    s_pos[t] = accP / fmaxf(cP, 1.f);
    hrow[t] = g_H[row * V + t];
    __syncthreads();

    const float* W0 = Wrel;                 // relation 0
    const float* W1 = Wrel + V * GH;        // relation 1
    float out = bias[t];
#pragma unroll 4
    for (int k = 0; k < V; k++) {
        out = fmaf(hrow[k], Wroot[k * GH + t], out);
        out = fmaf(s_neg[k], W0[k * GH + t], out);
        out = fmaf(s_pos[k], W1[k * GH + t], out);
    }
    g_H2[row * GH + t] = out;
}

// ---------------- K3: scatter  agg[b,i,:] = sum_j |A[b,i,j]| * H2[b,j,:] ----------------
__global__ void k_scatter(const float* __restrict__ A) {
    int row = blockIdx.x;           // b*N + i
    int b = row >> 8;
    int i = row & 255;
    int t = threadIdx.x;            // 128 threads
    const float* Ar = A + (b * N + i) * N;
    const float* H2b = g_H2 + b * N * GH;
    float acc = 0.f;
#pragma unroll 4
    for (int jj = 0; jj < N; jj++) {
        acc = fmaf(fabsf(Ar[jj]), H2b[jj * GH + t], acc);
    }
    g_agg[row * GH + t] = acc;
}

// ---------------- K4: agg = (relu(layernorm(agg)) @ law + lab).relu @ lbw + lbb ----------------
__global__ void k_normmlp(const float* __restrict__ norm_g, const float* __restrict__ norm_b,
                          const float* __restrict__ law, const float* __restrict__ lab,
                          const float* __restrict__ lbw, const float* __restrict__ lbb) {
    int row = blockIdx.x;
    int t = threadIdx.x;            // 128 threads
    __shared__ float red[GH];
    __shared__ float buf[GH];

    float x = g_agg[row * GH + t];
    // mean
    red[t] = x;
    __syncthreads();
    for (int s = GH / 2; s > 0; s >>= 1) {
        if (t < s) red[t] += red[t + s];
        __syncthreads();
    }
    float mean = red[0] * (1.f / GH);
    __syncthreads();
    // var (two-pass)
    float d = x - mean;
    red[t] = d * d;
    __syncthreads();
    for (int s = GH / 2; s > 0; s >>= 1) {
        if (t < s) red[t] += red[t + s];
        __syncthreads();
    }
    float var = red[0] * (1.f / GH);
    float xn = d * rsqrtf(var + EPS) * norm_g[t] + norm_b[t];
    buf[t] = fmaxf(xn, 0.f);
    __syncthreads();

    float a = lab[t];
#pragma unroll 8
    for (int k = 0; k < GH; k++) a = fmaf(buf[k], law[k * GH + t], a);
    a = fmaxf(a, 0.f);
    __syncthreads();
    buf[t] = a;
    __syncthreads();

    float o = lbb[t];
#pragma unroll 8
    for (int k = 0; k < GH; k++) o = fmaf(buf[k], lbw[k * GH + t], o);
    g_agg[row * GH + t] = o;
}

// ---------------- K5: H += agg ----------------
__global__ void k_add() {
    int idx = blockIdx.x * blockDim.x + threadIdx.x;
    if (idx < BN * GH) g_H[idx] += g_agg[idx];
}

// ---------------- K6: phi MLP ----------------
__global__ void k_phi(const float* __restrict__ w1, const float* __restrict__ b1,
                      const float* __restrict__ w2, const float* __restrict__ b2) {
    int row = blockIdx.x;
    int t = threadIdx.x;            // 256 threads
    __shared__ float hf[GH];
    __shared__ float h1[PHI];
    if (t < GH) hf[t] = g_H[row * GH + t];
    __syncthreads();
    float acc = b1[t];
#pragma unroll 8
    for (int k = 0; k < GH; k++) acc = fmaf(hf[k], w1[k * PHI + t], acc);
    h1[t] = fmaxf(acc, 0.f);
    __syncthreads();
    float acc2 = b2[t];
#pragma unroll 8
    for (int k = 0; k < PHI; k++) acc2 = fmaf(h1[k], w2[k * PHI + t], acc2);
    g_phi[row * PHI + t] = fmaxf(acc2, 0.f);
}

// ---------------- K7: masked pooling over N ----------------
__global__ void k_pool(const float* __restrict__ home_mask) {
    int b = blockIdx.x;             // 8 blocks
    int p = threadIdx.x;            // 256 threads
    const float* pb = g_phi + b * N * PHI;
    const float* hm = home_mask + b * N;
    float hs = 0.f, as = 0.f;
    for (int n = 0; n < N; n++) {
        float v = pb[n * PHI + p];
        float m = hm[n];
        hs = fmaf(v, m, hs);
        as = fmaf(v, 1.f - m, as);
    }
    g_sums[b * PHI + p] = hs;
    g_sums[B * PHI + b * PHI + p] = as;
}

// ---------------- K8: rho + antisym head ----------------
__global__ void k_rho(const float* __restrict__ w1, const float* __restrict__ b1,
                      const float* __restrict__ w2, float* __restrict__ out) {
    int b = blockIdx.x;             // 8 blocks
    int t = threadIdx.x;            // 128 threads
    __shared__ float hs[PHI];
    __shared__ float as[PHI];
    __shared__ float red[RHO];
    hs[t] = g_sums[b * PHI + t];
    hs[t + 128] = g_sums[b * PHI + t + 128];
    as[t] = g_sums[B * PHI + b * PHI + t];
    as[t + 128] = g_sums[B * PHI + b * PHI + t + 128];
    __syncthreads();
    float rh = b1[t], ra = b1[t];
#pragma unroll 8
    for (int k = 0; k < PHI; k++) {
        rh = fmaf(hs[k], w1[k * RHO + t], rh);
        ra = fmaf(as[k], w1[k * RHO + t], ra);
    }
    rh = fmaxf(rh, 0.f);
    ra = fmaxf(ra, 0.f);
    red[t] = (rh - ra) * w2[t];     // rho_b2 cancels in the difference
    __syncthreads();
    for (int s = RHO / 2; s > 0; s >>= 1) {
        if (t < s) red[t] += red[t + s];
        __syncthreads();
    }
    if (t == 0) out[b] = 0.5f + 0.5f * tanhf(red[0]);
}

// ---------------- launch ----------------
extern "C" void kernel_launch(void* const* d_in, const int* in_sizes, int n_in,
                              void* d_out, int out_size) {
    const float* A        = (const float*)d_in[0];
    const float* X        = (const float*)d_in[1];
    const float* home     = (const float*)d_in[2];
    const float* emb1_w   = (const float*)d_in[3];
    const float* emb1_b   = (const float*)d_in[4];
    const float* emb2_w   = (const float*)d_in[5];
    const float* emb2_b   = (const float*)d_in[6];
    const float* rgcn_w0  = (const float*)d_in[7];
    const float* root0    = (const float*)d_in[8];
    const float* bias0    = (const float*)d_in[9];
    const float* law0     = (const float*)d_in[10];
    const float* lab0     = (const float*)d_in[11];
    const float* lbw0     = (const float*)d_in[12];
    const float* lbb0     = (const float*)d_in[13];
    const float* rgcn_w1  = (const float*)d_in[14];
    const float* root1    = (const float*)d_in[15];
    const float* bias1    = (const float*)d_in[16];
    const float* law1     = (const float*)d_in[17];
    const float* lab1     = (const float*)d_in[18];
    const float* lbw1     = (const float*)d_in[19];
    const float* lbb1     = (const float*)d_in[20];
    const float* norm_g   = (const float*)d_in[21];
    const float* norm_b   = (const float*)d_in[22];
    const float* phi_w1   = (const float*)d_in[23];
    const float* phi_b1   = (const float*)d_in[24];
    const float* phi_w2   = (const float*)d_in[25];
    const float* phi_b2   = (const float*)d_in[26];
    const float* rho_w1   = (const float*)d_in[27];
    const float* rho_b1   = (const float*)d_in[28];
    const float* rho_w2   = (const float*)d_in[29];
    float* out = (float*)d_out;

    k_emb<<<BN, 128>>>(X, emb1_w, emb1_b, emb2_w, emb2_b);

    // block 0 (agg starts at zero; H unchanged)
    k_rgcn<<<BN, 128>>>(A, rgcn_w0, root0, bias0);
    k_scatter<<<BN, 128>>>(A);
    k_normmlp<<<BN, 128>>>(norm_g, norm_b, law0, lab0, lbw0, lbb0);
    k_add<<<(BN * GH + 255) / 256, 256>>>();   // H = H + agg0

    // block 1
    k_rgcn<<<BN, 128>>>(A, rgcn_w1, root1, bias1);
    k_scatter<<<BN, 128>>>(A);
    k_normmlp<<<BN, 128>>>(norm_g, norm_b, law1, lab1, lbw1, lbb1);
    k_add<<<(BN * GH + 255) / 256, 256>>>();   // H = H + agg1  (final H)

    k_phi<<<BN, 256>>>(phi_w1, phi_b1, phi_w2, phi_b2);
    k_pool<<<B, 256>>>(home);
    k_rho<<<B, 128>>>(rho_w1, rho_b1, rho_w2, out);
}